// round 1
// baseline (speedup 1.0000x reference)
#include <cuda_runtime.h>
#include <cstdint>

#define Pn      96000
#define Mn      32
#define COUTn   64
#define NXn     432
#define NYn     496
#define NBn     8
#define NCELL   (NXn*NYn)          // 214272
#define TOTCELL (NBn*NCELL)        // 1714176
#define NSAMP   (Pn*Mn)            // 3072000

#define ABLOCKS 592
#define AWARPS  (ABLOCKS*8)        // 4736
#define CBLOCKS 1184
#define CWARPS  (CBLOCKS*8)        // 9472

// ---------------- scratch (static device globals; no allocations) ----------
__device__ int   g_winner[TOTCELL];                  // 6.9 MB
__device__ float g_part[AWARPS][72];                 // per-warp moment partials
__device__ float g_pv[Pn*COUTn];                     // 24.6 MB pooled features
__device__ float g_scale[COUTn];
__device__ float g_shift[COUTn];

// ---------------- f32x2 packed helpers -------------------------------------
typedef unsigned long long u64;
__device__ __forceinline__ u64 pk2(float lo, float hi) {
    u64 r; asm("mov.b64 %0, {%1, %2};" : "=l"(r) : "f"(lo), "f"(hi)); return r;
}
__device__ __forceinline__ void upk2(u64 v, float& lo, float& hi) {
    asm("mov.b64 {%0, %1}, %2;" : "=f"(lo), "=f"(hi) : "l"(v));
}
__device__ __forceinline__ u64 ffma2(u64 a, u64 b, u64 c) {
    u64 d; asm("fma.rn.f32x2 %0, %1, %2, %3;" : "=l"(d) : "l"(a), "l"(b), "l"(c)); return d;
}

// ---------------- kernel 0: reset winner array ------------------------------
__global__ void __launch_bounds__(256) kfill_winner() {
    int i = blockIdx.x * 256 + threadIdx.x;          // TOTCELL/4 = 428544 = 1674*256
    reinterpret_cast<int4*>(g_winner)[i] = make_int4(-1, -1, -1, -1);
}

// ---------------- kernel A: moment stats + winner atomicMax ----------------
// warp-per-pillar (lane = point m). Accumulates 10 means + 55 upper-tri
// second moments of the 10-dim feature vector, block-free tree reduction.
__global__ void __launch_bounds__(256) kstats(const float4* __restrict__ pil,
                                              const int4*  __restrict__ coords,
                                              const int*   __restrict__ npts) {
    int lane = threadIdx.x & 31;
    int warp = (blockIdx.x * blockDim.x + threadIdx.x) >> 5;

    float acc[65];
    #pragma unroll
    for (int k = 0; k < 65; k++) acc[k] = 0.f;

    for (int p = warp; p < Pn; p += AWARPS) {
        float4 pt = pil[p * Mn + lane];
        float sx = pt.x, sy = pt.y, sz = pt.z;
        #pragma unroll
        for (int off = 16; off; off >>= 1) {
            sx += __shfl_xor_sync(~0u, sx, off);
            sy += __shfl_xor_sync(~0u, sy, off);
            sz += __shfl_xor_sync(~0u, sz, off);
        }
        float n = (float)npts[p];
        int4 c = coords[p];                      // (b, z, y, x)
        float cxf = fmaf((float)c.w, 0.16f, 0.08f);
        float cyf = fmaf((float)c.z, 0.16f, -39.6f);
        float czf = fmaf((float)c.y, 4.0f,  -1.0f);

        float f[10];
        f[0] = pt.x; f[1] = pt.y; f[2] = pt.z; f[3] = pt.w;
        f[4] = pt.x - sx / n; f[5] = pt.y - sy / n; f[6] = pt.z - sz / n;
        f[7] = pt.x - cxf;    f[8] = pt.y - cyf;    f[9] = pt.z - czf;

        int k = 0;
        #pragma unroll
        for (int i = 0; i < 10; i++) {
            acc[55 + i] += f[i];
            #pragma unroll
            for (int j = i; j < 10; j++) acc[k++] += f[i] * f[j];
        }
        if (lane == 0) {
            int flat = c.x * NCELL + c.y + c.z * NXn + c.w;
            atomicMax(&g_winner[flat], p);       // highest pillar index wins (scatter-set order)
        }
    }
    #pragma unroll
    for (int k = 0; k < 65; k++) {
        float v = acc[k];
        #pragma unroll
        for (int off = 16; off; off >>= 1) v += __shfl_xor_sync(~0u, v, off);
        acc[k] = v;
    }
    if (lane == 0) {
        #pragma unroll
        for (int k = 0; k < 65; k++) g_part[warp][k] = acc[k];
    }
}

// ---------------- kernel B: finalize BN scale/shift -------------------------
__global__ void __launch_bounds__(1024) kbn(const float* __restrict__ W,
                                            const float* __restrict__ gamma,
                                            const float* __restrict__ beta) {
    __shared__ float tot[65];
    __shared__ float Sfull[10][10];
    __shared__ float mfs[10];
    int tid = threadIdx.x, lane = tid & 31, w = tid >> 5;

    for (int k = w; k < 65; k += 32) {
        float s = 0.f;
        for (int j = lane; j < AWARPS; j += 32) s += g_part[j][k];
        #pragma unroll
        for (int off = 16; off; off >>= 1) s += __shfl_xor_sync(~0u, s, off);
        if (lane == 0) tot[k] = s;
    }
    __syncthreads();
    if (tid < 100) {
        int i = tid / 10, j = tid % 10;
        int a = min(i, j), b = max(i, j);
        Sfull[i][j] = tot[10 * a - (a * (a - 1)) / 2 + (b - a)];
    }
    if (tid < 10) mfs[tid] = tot[55 + tid];
    __syncthreads();
    if (tid < COUTn) {
        int c = tid;
        float wc[10];
        #pragma unroll
        for (int i = 0; i < 10; i++) wc[i] = W[i * COUTn + c];
        float mu = 0.f, e2 = 0.f;
        #pragma unroll
        for (int i = 0; i < 10; i++) {
            mu += mfs[i] * wc[i];
            float t = 0.f;
            #pragma unroll
            for (int j = 0; j < 10; j++) t += Sfull[i][j] * wc[j];
            e2 += wc[i] * t;
        }
        mu = mu / (float)NSAMP;
        e2 = e2 / (float)NSAMP;
        float var = e2 - mu * mu;
        float sc = gamma[c] * rsqrtf(var + 1e-3f);
        g_scale[c] = sc;
        g_shift[c] = beta[c] - mu * sc;
    }
}

// ---------------- kernel C: per-pillar GEMM + BN + ReLU + max over M --------
// warp-per-pillar, persistent. lane = point m for feature build; lane handles
// channels (lane, lane+32) for the GEMM. Inner loop uses packed f32x2 FFMA
// over point-pairs (feats stored transposed [i][m] in shared).
__global__ void __launch_bounds__(256) kpv(const float4* __restrict__ pil,
                                           const int4*  __restrict__ coords,
                                           const int*   __restrict__ npts,
                                           const float* __restrict__ W) {
    __shared__ float fs[8][10][32];
    int lane = threadIdx.x & 31;
    int wInB = threadIdx.x >> 5;
    int warp = (blockIdx.x * blockDim.x + threadIdx.x) >> 5;
    int c0 = lane, c1 = lane + 32;

    u64 w0[10], w1[10];
    #pragma unroll
    for (int i = 0; i < 10; i++) {
        float a = W[i * COUTn + c0]; w0[i] = pk2(a, a);
        float b = W[i * COUTn + c1]; w1[i] = pk2(b, b);
    }
    float sc0 = g_scale[c0], sh0 = g_shift[c0];
    float sc1 = g_scale[c1], sh1 = g_shift[c1];

    for (int p = warp; p < Pn; p += CWARPS) {
        float4 pt = pil[p * Mn + lane];
        float sx = pt.x, sy = pt.y, sz = pt.z;
        #pragma unroll
        for (int off = 16; off; off >>= 1) {
            sx += __shfl_xor_sync(~0u, sx, off);
            sy += __shfl_xor_sync(~0u, sy, off);
            sz += __shfl_xor_sync(~0u, sz, off);
        }
        float n = (float)npts[p];
        int4 c = coords[p];
        float cxf = fmaf((float)c.w, 0.16f, 0.08f);
        float cyf = fmaf((float)c.z, 0.16f, -39.6f);
        float czf = fmaf((float)c.y, 4.0f,  -1.0f);

        fs[wInB][0][lane] = pt.x;
        fs[wInB][1][lane] = pt.y;
        fs[wInB][2][lane] = pt.z;
        fs[wInB][3][lane] = pt.w;
        fs[wInB][4][lane] = pt.x - sx / n;
        fs[wInB][5][lane] = pt.y - sy / n;
        fs[wInB][6][lane] = pt.z - sz / n;
        fs[wInB][7][lane] = pt.x - cxf;
        fs[wInB][8][lane] = pt.y - cyf;
        fs[wInB][9][lane] = pt.z - czf;
        __syncwarp();

        float hmax0 = -3.402823466e38f, hmin0 = 3.402823466e38f;
        float hmax1 = -3.402823466e38f, hmin1 = 3.402823466e38f;
        #pragma unroll
        for (int mm = 0; mm < 16; mm++) {
            u64 a0 = 0ull, a1 = 0ull;
            #pragma unroll
            for (int i = 0; i < 10; i++) {
                u64 fp = *reinterpret_cast<const u64*>(&fs[wInB][i][2 * mm]);
                a0 = ffma2(fp, w0[i], a0);
                a1 = ffma2(fp, w1[i], a1);
            }
            float lo, hi;
            upk2(a0, lo, hi);
            hmax0 = fmaxf(hmax0, fmaxf(lo, hi));
            hmin0 = fminf(hmin0, fminf(lo, hi));
            upk2(a1, lo, hi);
            hmax1 = fmaxf(hmax1, fmaxf(lo, hi));
            hmin1 = fminf(hmin1, fminf(lo, hi));
        }
        // max_m relu(h*s+b) == relu(max_m(h*s+b)); max picks hmax if s>=0 else hmin
        float h0 = (sc0 >= 0.f) ? hmax0 : hmin0;
        float h1 = (sc1 >= 0.f) ? hmax1 : hmin1;
        g_pv[p * COUTn + c0] = fmaxf(fmaf(h0, sc0, sh0), 0.f);
        g_pv[p * COUTn + c1] = fmaxf(fmaf(h1, sc1, sh1), 0.f);
        __syncwarp();
    }
}

// ---------------- kernel Z: write zero quads (depends only on winner) -------
__global__ void __launch_bounds__(256) kzero(float* __restrict__ out) {
    int q = blockIdx.x * 256 + threadIdx.x;          // quad within one batch plane
    if (q >= NCELL / 4) return;
    int b = blockIdx.y;
    int4 w = reinterpret_cast<const int4*>(g_winner)[b * (NCELL / 4) + q];
    if (max(max(w.x, w.y), max(w.z, w.w)) >= 0) return;   // occupied -> kscatter's quad
    float4 z = make_float4(0.f, 0.f, 0.f, 0.f);
    float* base = out + (size_t)b * COUTn * NCELL + (size_t)q * 4;
    #pragma unroll
    for (int cidx = 0; cidx < COUTn; cidx++)
        *reinterpret_cast<float4*>(base + (size_t)cidx * NCELL) = z;
}

// ---------------- kernel S: gather pv into occupied quads -------------------
__global__ void __launch_bounds__(256) kscatter(float* __restrict__ out) {
    int q = blockIdx.x * 256 + threadIdx.x;
    if (q >= NCELL / 4) return;
    int b = blockIdx.y;
    int4 w = reinterpret_cast<const int4*>(g_winner)[b * (NCELL / 4) + q];
    if (max(max(w.x, w.y), max(w.z, w.w)) < 0) return;    // empty -> kzero's quad
    const float4 z = make_float4(0.f, 0.f, 0.f, 0.f);
    float* base = out + (size_t)b * COUTn * NCELL + (size_t)q * 4;
    #pragma unroll 4
    for (int cc = 0; cc < COUTn; cc += 4) {
        float4 r0 = (w.x >= 0) ? *reinterpret_cast<const float4*>(&g_pv[w.x * COUTn + cc]) : z;
        float4 r1 = (w.y >= 0) ? *reinterpret_cast<const float4*>(&g_pv[w.y * COUTn + cc]) : z;
        float4 r2 = (w.z >= 0) ? *reinterpret_cast<const float4*>(&g_pv[w.z * COUTn + cc]) : z;
        float4 r3 = (w.w >= 0) ? *reinterpret_cast<const float4*>(&g_pv[w.w * COUTn + cc]) : z;
        *reinterpret_cast<float4*>(base + (size_t)(cc + 0) * NCELL) = make_float4(r0.x, r1.x, r2.x, r3.x);
        *reinterpret_cast<float4*>(base + (size_t)(cc + 1) * NCELL) = make_float4(r0.y, r1.y, r2.y, r3.y);
        *reinterpret_cast<float4*>(base + (size_t)(cc + 2) * NCELL) = make_float4(r0.z, r1.z, r2.z, r3.z);
        *reinterpret_cast<float4*>(base + (size_t)(cc + 3) * NCELL) = make_float4(r0.w, r1.w, r2.w, r3.w);
    }
}

// ---------------- launch -----------------------------------------------------
extern "C" void kernel_launch(void* const* d_in, const int* in_sizes, int n_in,
                              void* d_out, int out_size) {
    const float4* pil    = (const float4*)d_in[0];   // (96000, 32, 4) f32
    const int4*   coords = (const int4*)  d_in[1];   // (96000, 4) i32
    const int*    npts   = (const int*)   d_in[2];   // (96000,)   i32
    const float*  W      = (const float*) d_in[3];   // (10, 64)   f32
    const float*  gamma  = (const float*) d_in[4];   // (64,)
    const float*  beta   = (const float*) d_in[5];   // (64,)
    float* out = (float*)d_out;
    (void)in_sizes; (void)n_in; (void)out_size;

    // Lazy init of fork stream/events on the (uncaptured) correctness call.
    static cudaStream_t s2 = nullptr;
    static cudaEvent_t evA = nullptr, evB = nullptr;
    if (!s2) {
        cudaStreamCreateWithFlags(&s2, cudaStreamNonBlocking);
        cudaEventCreateWithFlags(&evA, cudaEventDisableTiming);
        cudaEventCreateWithFlags(&evB, cudaEventDisableTiming);
    }

    dim3 qgrid((NCELL / 4 + 255) / 256, NBn);        // (210, 8)

    kfill_winner<<<TOTCELL / 4 / 256, 256>>>();
    kstats<<<ABLOCKS, 256>>>(pil, coords, npts);

    // fork: zero-quad writer only needs the winner array
    cudaEventRecord(evA, 0);
    cudaStreamWaitEvent(s2, evA, 0);
    kzero<<<qgrid, 256, 0, s2>>>(out);
    cudaEventRecord(evB, s2);

    kbn<<<1, 1024>>>(W, gamma, beta);
    kpv<<<CBLOCKS, 256>>>(pil, coords, npts, W);
    kscatter<<<qgrid, 256>>>(out);                   // disjoint quads vs kzero

    cudaStreamWaitEvent(0, evB, 0);                  // join before capture end
}

// round 3
// speedup vs baseline: 1.1317x; 1.1317x over previous
#include <cuda_runtime.h>
#include <cstdint>

#define Pn      96000
#define Mn      32
#define COUTn   64
#define NXn     432
#define NYn     496
#define NBn     8
#define NCELL   (NXn*NYn)          // 214272
#define TOTCELL (NBn*NCELL)        // 1714176
#define NSAMP   (Pn*Mn)            // 3072000

#define ABLOCKS 592
#define AWARPS  (ABLOCKS*8)        // 4736
#define CBLOCKS 1184
#define CWARPS  (CBLOCKS*8)        // 9472

// ---------------- scratch (static device globals; no allocations) ----------
__device__ int   g_winner[TOTCELL];                  // 6.9 MB
__device__ float g_part[ABLOCKS][72];                // per-BLOCK moment partials
__device__ float g_pv[Pn*COUTn];                     // 24.6 MB pooled features
__device__ float g_wsc[10*COUTn];                    // W * bn_scale
__device__ float g_shift[COUTn];

// ---------------- f32x2 packed helpers -------------------------------------
typedef unsigned long long u64;
__device__ __forceinline__ u64 pk2(float lo, float hi) {
    u64 r; asm("mov.b64 %0, {%1, %2};" : "=l"(r) : "f"(lo), "f"(hi)); return r;
}
__device__ __forceinline__ void upk2(u64 v, float& lo, float& hi) {
    asm("mov.b64 {%0, %1}, %2;" : "=f"(lo), "=f"(hi) : "l"(v));
}
__device__ __forceinline__ u64 ffma2(u64 a, u64 b, u64 c) {
    u64 d; asm("fma.rn.f32x2 %0, %1, %2, %3;" : "=l"(d) : "l"(a), "l"(b), "l"(c)); return d;
}

// ---------------- kernel 0: reset winner array ------------------------------
__global__ void __launch_bounds__(256) kfill_winner() {
    int i = blockIdx.x * 256 + threadIdx.x;          // TOTCELL/4 = 428544 = 1674*256
    reinterpret_cast<int4*>(g_winner)[i] = make_int4(-1, -1, -1, -1);
}

// ---------------- kernel W: winner resolution (scatter-set order) -----------
__global__ void __launch_bounds__(256) kwin(const int4* __restrict__ coords) {
    int p = blockIdx.x * 256 + threadIdx.x;
    if (p >= Pn) return;
    int4 c = coords[p];                              // (b, z, y, x)
    int flat = c.x * NCELL + c.y + c.z * NXn + c.w;
    atomicMax(&g_winner[flat], p);                   // highest pillar index wins
}

// ---------------- kernel A: moment stats (block-level partials) -------------
// warp-per-pillar (lane = point m). Accumulates 10 means + 55 upper-tri
// second moments of the 10-dim feature vector.
__global__ void __launch_bounds__(256) kstats(const float4* __restrict__ pil,
                                              const int4*  __restrict__ coords,
                                              const int*   __restrict__ npts) {
    __shared__ float sm[8][66];
    int lane = threadIdx.x & 31;
    int wInB = threadIdx.x >> 5;
    int warp = (blockIdx.x * blockDim.x + threadIdx.x) >> 5;

    float acc[65];
    #pragma unroll
    for (int k = 0; k < 65; k++) acc[k] = 0.f;

    for (int p = warp; p < Pn; p += AWARPS) {
        float4 pt = pil[p * Mn + lane];
        float sx = pt.x, sy = pt.y, sz = pt.z;
        #pragma unroll
        for (int off = 16; off; off >>= 1) {
            sx += __shfl_xor_sync(~0u, sx, off);
            sy += __shfl_xor_sync(~0u, sy, off);
            sz += __shfl_xor_sync(~0u, sz, off);
        }
        float n = (float)npts[p];
        int4 c = coords[p];                      // (b, z, y, x)
        float cxf = fmaf((float)c.w, 0.16f, 0.08f);
        float cyf = fmaf((float)c.z, 0.16f, -39.6f);
        float czf = fmaf((float)c.y, 4.0f,  -1.0f);

        float f[10];
        f[0] = pt.x; f[1] = pt.y; f[2] = pt.z; f[3] = pt.w;
        f[4] = pt.x - sx / n; f[5] = pt.y - sy / n; f[6] = pt.z - sz / n;
        f[7] = pt.x - cxf;    f[8] = pt.y - cyf;    f[9] = pt.z - czf;

        int k = 0;
        #pragma unroll
        for (int i = 0; i < 10; i++) {
            acc[55 + i] += f[i];
            #pragma unroll
            for (int j = i; j < 10; j++) acc[k++] += f[i] * f[j];
        }
    }
    #pragma unroll
    for (int k = 0; k < 65; k++) {
        float v = acc[k];
        #pragma unroll
        for (int off = 16; off; off >>= 1) v += __shfl_xor_sync(~0u, v, off);
        acc[k] = v;
    }
    if (lane == 0) {
        #pragma unroll
        for (int k = 0; k < 65; k++) sm[wInB][k] = acc[k];
    }
    __syncthreads();
    int tid = threadIdx.x;
    if (tid < 65) {
        float s = 0.f;
        #pragma unroll
        for (int w = 0; w < 8; w++) s += sm[w][tid];
        g_part[blockIdx.x][tid] = s;
    }
}

// ---------------- kernel B: finalize BN; fold scale into weights ------------
__global__ void __launch_bounds__(1024) kbn(const float* __restrict__ W,
                                            const float* __restrict__ gamma,
                                            const float* __restrict__ beta) {
    __shared__ float tot[65];
    __shared__ float Sfull[10][10];
    __shared__ float mfs[10];
    __shared__ float s_scale[COUTn];
    int tid = threadIdx.x, lane = tid & 31, w = tid >> 5;

    for (int k = w; k < 65; k += 32) {
        float s = 0.f;
        for (int j = lane; j < ABLOCKS; j += 32) s += g_part[j][k];
        #pragma unroll
        for (int off = 16; off; off >>= 1) s += __shfl_xor_sync(~0u, s, off);
        if (lane == 0) tot[k] = s;
    }
    __syncthreads();
    if (tid < 100) {
        int i = tid / 10, j = tid % 10;
        int a = min(i, j), b = max(i, j);
        Sfull[i][j] = tot[10 * a - (a * (a - 1)) / 2 + (b - a)];
    }
    if (tid < 10) mfs[tid] = tot[55 + tid];
    __syncthreads();
    if (tid < COUTn) {
        int c = tid;
        float wc[10];
        #pragma unroll
        for (int i = 0; i < 10; i++) wc[i] = W[i * COUTn + c];
        float mu = 0.f, e2 = 0.f;
        #pragma unroll
        for (int i = 0; i < 10; i++) {
            mu += mfs[i] * wc[i];
            float t = 0.f;
            #pragma unroll
            for (int j = 0; j < 10; j++) t += Sfull[i][j] * wc[j];
            e2 += wc[i] * t;
        }
        mu = mu / (float)NSAMP;
        e2 = e2 / (float)NSAMP;
        float var = e2 - mu * mu;
        float sc = gamma[c] * rsqrtf(var + 1e-3f);
        s_scale[c] = sc;
        g_shift[c] = beta[c] - mu * sc;
    }
    __syncthreads();
    if (tid < 10 * COUTn) {
        int c = tid & (COUTn - 1);
        g_wsc[tid] = W[tid] * s_scale[c];            // fold BN scale into W
    }
}

// ---------------- kernel C: per-pillar GEMM(+scale) + max over M + shift ----
// warp-per-pillar, persistent. lane = point m for feature build; lane handles
// channels (lane, lane+32). Packed f32x2 FFMA over point-pairs.
__global__ void __launch_bounds__(256) kpv(const float4* __restrict__ pil,
                                           const int4*  __restrict__ coords,
                                           const int*   __restrict__ npts) {
    __shared__ float fs[8][10][32];
    int lane = threadIdx.x & 31;
    int wInB = threadIdx.x >> 5;
    int warp = (blockIdx.x * blockDim.x + threadIdx.x) >> 5;
    int c0 = lane, c1 = lane + 32;

    u64 w0[10], w1[10];
    #pragma unroll
    for (int i = 0; i < 10; i++) {
        float a = g_wsc[i * COUTn + c0]; w0[i] = pk2(a, a);
        float b = g_wsc[i * COUTn + c1]; w1[i] = pk2(b, b);
    }
    float sh0 = g_shift[c0], sh1 = g_shift[c1];

    for (int p = warp; p < Pn; p += CWARPS) {
        float4 pt = pil[p * Mn + lane];
        float sx = pt.x, sy = pt.y, sz = pt.z;
        #pragma unroll
        for (int off = 16; off; off >>= 1) {
            sx += __shfl_xor_sync(~0u, sx, off);
            sy += __shfl_xor_sync(~0u, sy, off);
            sz += __shfl_xor_sync(~0u, sz, off);
        }
        float n = (float)npts[p];
        int4 c = coords[p];
        float cxf = fmaf((float)c.w, 0.16f, 0.08f);
        float cyf = fmaf((float)c.z, 0.16f, -39.6f);
        float czf = fmaf((float)c.y, 4.0f,  -1.0f);

        fs[wInB][0][lane] = pt.x;
        fs[wInB][1][lane] = pt.y;
        fs[wInB][2][lane] = pt.z;
        fs[wInB][3][lane] = pt.w;
        fs[wInB][4][lane] = pt.x - sx / n;
        fs[wInB][5][lane] = pt.y - sy / n;
        fs[wInB][6][lane] = pt.z - sz / n;
        fs[wInB][7][lane] = pt.x - cxf;
        fs[wInB][8][lane] = pt.y - cyf;
        fs[wInB][9][lane] = pt.z - czf;
        __syncwarp();

        // weights carry bn scale -> max pool applies directly, no min path
        float hmax0 = -3.402823466e38f;
        float hmax1 = -3.402823466e38f;
        #pragma unroll
        for (int mm = 0; mm < 16; mm++) {
            u64 a0 = 0ull, a1 = 0ull;
            #pragma unroll
            for (int i = 0; i < 10; i++) {
                u64 fp = *reinterpret_cast<const u64*>(&fs[wInB][i][2 * mm]);
                a0 = ffma2(fp, w0[i], a0);
                a1 = ffma2(fp, w1[i], a1);
            }
            float lo, hi;
            upk2(a0, lo, hi);
            hmax0 = fmaxf(hmax0, fmaxf(lo, hi));
            upk2(a1, lo, hi);
            hmax1 = fmaxf(hmax1, fmaxf(lo, hi));
        }
        g_pv[p * COUTn + c0] = fmaxf(hmax0 + sh0, 0.f);
        g_pv[p * COUTn + c1] = fmaxf(hmax1 + sh1, 0.f);
        __syncwarp();
    }
}

// ---------------- kernel Z: write zero quads (depends only on winner) -------
__global__ void __launch_bounds__(256) kzero(float* __restrict__ out) {
    int q = blockIdx.x * 256 + threadIdx.x;          // quad within one batch plane
    if (q >= NCELL / 4) return;
    int b = blockIdx.y;
    int4 w = reinterpret_cast<const int4*>(g_winner)[b * (NCELL / 4) + q];
    if (max(max(w.x, w.y), max(w.z, w.w)) >= 0) return;   // occupied -> kscatter's quad
    float4 z = make_float4(0.f, 0.f, 0.f, 0.f);
    float* base = out + (size_t)b * COUTn * NCELL + (size_t)q * 4;
    #pragma unroll
    for (int cidx = 0; cidx < COUTn; cidx++)
        *reinterpret_cast<float4*>(base + (size_t)cidx * NCELL) = z;
}

// ---------------- kernel S: gather pv into occupied quads -------------------
__global__ void __launch_bounds__(256) kscatter(float* __restrict__ out) {
    int q = blockIdx.x * 256 + threadIdx.x;
    if (q >= NCELL / 4) return;
    int b = blockIdx.y;
    int4 w = reinterpret_cast<const int4*>(g_winner)[b * (NCELL / 4) + q];
    if (max(max(w.x, w.y), max(w.z, w.w)) < 0) return;    // empty -> kzero's quad
    const float4 z = make_float4(0.f, 0.f, 0.f, 0.f);
    float* base = out + (size_t)b * COUTn * NCELL + (size_t)q * 4;
    #pragma unroll 4
    for (int cc = 0; cc < COUTn; cc += 4) {
        float4 r0 = (w.x >= 0) ? *reinterpret_cast<const float4*>(&g_pv[w.x * COUTn + cc]) : z;
        float4 r1 = (w.y >= 0) ? *reinterpret_cast<const float4*>(&g_pv[w.y * COUTn + cc]) : z;
        float4 r2 = (w.z >= 0) ? *reinterpret_cast<const float4*>(&g_pv[w.z * COUTn + cc]) : z;
        float4 r3 = (w.w >= 0) ? *reinterpret_cast<const float4*>(&g_pv[w.w * COUTn + cc]) : z;
        *reinterpret_cast<float4*>(base + (size_t)(cc + 0) * NCELL) = make_float4(r0.x, r1.x, r2.x, r3.x);
        *reinterpret_cast<float4*>(base + (size_t)(cc + 1) * NCELL) = make_float4(r0.y, r1.y, r2.y, r3.y);
        *reinterpret_cast<float4*>(base + (size_t)(cc + 2) * NCELL) = make_float4(r0.z, r1.z, r2.z, r3.z);
        *reinterpret_cast<float4*>(base + (size_t)(cc + 3) * NCELL) = make_float4(r0.w, r1.w, r2.w, r3.w);
    }
}

// ---------------- launch -----------------------------------------------------
extern "C" void kernel_launch(void* const* d_in, const int* in_sizes, int n_in,
                              void* d_out, int out_size) {
    const float4* pil    = (const float4*)d_in[0];   // (96000, 32, 4) f32
    const int4*   coords = (const int4*)  d_in[1];   // (96000, 4) i32
    const int*    npts   = (const int*)   d_in[2];   // (96000,)   i32
    const float*  W      = (const float*) d_in[3];   // (10, 64)   f32
    const float*  gamma  = (const float*) d_in[4];   // (64,)
    const float*  beta   = (const float*) d_in[5];   // (64,)
    float* out = (float*)d_out;
    (void)in_sizes; (void)n_in; (void)out_size;

    // Lazy init of fork stream/events on the (uncaptured) correctness call.
    static cudaStream_t s2 = nullptr;
    static cudaEvent_t evA = nullptr, evB = nullptr;
    if (!s2) {
        cudaStreamCreateWithFlags(&s2, cudaStreamNonBlocking);
        cudaEventCreateWithFlags(&evA, cudaEventDisableTiming);
        cudaEventCreateWithFlags(&evB, cudaEventDisableTiming);
    }

    dim3 qgrid((NCELL / 4 + 255) / 256, NBn);        // (210, 8)

    kfill_winner<<<TOTCELL / 4 / 256, 256>>>();      // launch 1
    kwin<<<(Pn + 255) / 256, 256>>>(coords);         // launch 2

    // fork immediately: zero-quad writer only needs the winner array and
    // overlaps the entire compute chain below
    cudaEventRecord(evA, 0);
    cudaStreamWaitEvent(s2, evA, 0);
    kzero<<<qgrid, 256, 0, s2>>>(out);               // launch 3 (stream s2)
    cudaEventRecord(evB, s2);

    kstats<<<ABLOCKS, 256>>>(pil, coords, npts);     // launch 4
    kbn<<<1, 1024>>>(W, gamma, beta);                // launch 5
    kpv<<<CBLOCKS, 256>>>(pil, coords, npts);        // launch 6  <- ncu -s 5 -c 1
    kscatter<<<qgrid, 256>>>(out);                   // launch 7 (disjoint quads vs kzero)

    cudaStreamWaitEvent(0, evB, 0);                  // join before capture end
}

// round 5
// speedup vs baseline: 1.3472x; 1.1905x over previous
#include <cuda_runtime.h>
#include <cstdint>

#define Pn      96000
#define Mn      32
#define COUTn   64
#define NXn     432
#define NYn     496
#define NBn     8
#define NCELL   (NXn*NYn)          // 214272
#define TOTCELL (NBn*NCELL)        // 1714176
#define NSAMP   (Pn*Mn)            // 3072000

#define SBLOCKS 1184
#define SWARPS  (SBLOCKS*8)        // 9472
#define CBLOCKS 1184
#define CWARPS  (CBLOCKS*8)        // 9472

// ---------------- scratch (static device globals; no allocations) ----------
__device__ int   g_winner[TOTCELL];                  // 6.9 MB
__device__ float g_part[SBLOCKS][80];                // per-block moment partials
__device__ float g_pv[Pn*COUTn];                     // 24.6 MB pooled features
__device__ float g_wf[10*COUTn];                     // rows0-3: combined*scale, rows4-9: W*scale
__device__ float g_shift[COUTn];

// ---------------- f32x2 packed helpers (sm_100+ packed fp32 family) --------
// NOTE: only fma/add/mul exist in f32x2 form; max must be scalar FMNMX.
typedef unsigned long long u64;
__device__ __forceinline__ u64 pk2(float lo, float hi) {
    u64 r; asm("mov.b64 %0, {%1, %2};" : "=l"(r) : "f"(lo), "f"(hi)); return r;
}
__device__ __forceinline__ void upk2(u64 v, float& lo, float& hi) {
    asm("mov.b64 {%0, %1}, %2;" : "=f"(lo), "=f"(hi) : "l"(v));
}
__device__ __forceinline__ u64 ffma2(u64 a, u64 b, u64 c) {
    u64 d; asm("fma.rn.f32x2 %0, %1, %2, %3;" : "=l"(d) : "l"(a), "l"(b), "l"(c)); return d;
}
__device__ __forceinline__ u64 fmul2(u64 a, u64 b) {
    u64 d; asm("mul.rn.f32x2 %0, %1, %2;" : "=l"(d) : "l"(a), "l"(b)); return d;
}

// ---------------- kernel 0: reset winner array ------------------------------
__global__ void __launch_bounds__(256) kfill_winner() {
    int i = blockIdx.x * 256 + threadIdx.x;          // TOTCELL/4 = 428544 = 1674*256
    reinterpret_cast<int4*>(g_winner)[i] = make_int4(-1, -1, -1, -1);
}

// ---------------- kernel W: winner resolution (scatter-set order) -----------
__global__ void __launch_bounds__(256) kwin(const int4* __restrict__ coords) {
    int p = blockIdx.x * 256 + threadIdx.x;
    if (p >= Pn) return;
    int4 c = coords[p];                              // (b, z, y, x)
    int flat = c.x * NCELL + c.y + c.z * NXn + c.w;
    atomicMax(&g_winner[flat], p);                   // highest pillar index wins
}

// ---------------- kernel A: decomposed moment stats -------------------------
// Features f_i = u_i - k_i (u in {x,y,z,w}, k per-pillar constants).
// Point-level: 14 raw moments (4 first + 10 second) per thread.
// Pillar-level: 66 scalar products q[6] (x) r[11] distributed across lanes:
//   q = {a,b,c,d,e,g} (means + centers), r = {Sx,Sy,Sz,Sw, q..., 32}.
//   slot s -> q[s/11] * r[s%11]; lane l owns slots l, l+32, l+64 (<66 used).
__global__ void __launch_bounds__(256) kstats(const float4* __restrict__ pil,
                                              const int4*  __restrict__ coords,
                                              const int*   __restrict__ npts) {
    __shared__ float sslot[8][66];
    __shared__ float su[8][14];
    int lane = threadIdx.x & 31;
    int wInB = threadIdx.x >> 5;
    int warp = (blockIdx.x * 256 + threadIdx.x) >> 5;

    int s0 = lane, s1 = lane + 32, s2v = lane + 64;
    int i0 = s0 / 11, j0 = s0 % 11;
    int i1 = s1 / 11, j1 = s1 % 11;
    int i2 = s2v / 11, j2 = s2v % 11;               // junk for lane>=2, never read

    float u1[4]  = {0.f, 0.f, 0.f, 0.f};
    float u2[10] = {0.f,0.f,0.f,0.f,0.f,0.f,0.f,0.f,0.f,0.f};
    float a0 = 0.f, a1 = 0.f, a2 = 0.f;

    for (int p = warp; p < Pn; p += SWARPS) {
        float4 pt = pil[p * Mn + lane];
        float x = pt.x, y = pt.y, z = pt.z, w = pt.w;
        u1[0] += x; u1[1] += y; u1[2] += z; u1[3] += w;
        u2[0] += x*x; u2[1] += x*y; u2[2] += x*z; u2[3] += x*w;
        u2[4] += y*y; u2[5] += y*z; u2[6] += y*w;
        u2[7] += z*z; u2[8] += z*w; u2[9] += w*w;

        float sx = x, sy = y, sz = z, sw = w;
        #pragma unroll
        for (int off = 16; off; off >>= 1) {
            sx += __shfl_xor_sync(~0u, sx, off);
            sy += __shfl_xor_sync(~0u, sy, off);
            sz += __shfl_xor_sync(~0u, sz, off);
            sw += __shfl_xor_sync(~0u, sw, off);
        }
        float inv = __fdividef(1.0f, (float)npts[p]);
        int4 cd = coords[p];
        float qa = sx * inv, qb = sy * inv, qc = sz * inv;
        float qd = fmaf((float)cd.w, 0.16f, 0.08f);
        float qe = fmaf((float)cd.z, 0.16f, -39.6f);
        float qg = fmaf((float)cd.y, 4.0f,  -1.0f);

        float qsel = lane==0?qa: lane==1?qb: lane==2?qc: lane==3?qd: lane==4?qe: qg;
        float rsel = lane==0?sx: lane==1?sy: lane==2?sz: lane==3?sw:
                     lane==4?qa: lane==5?qb: lane==6?qc: lane==7?qd:
                     lane==8?qe: lane==9?qg: 32.0f;

        a0 += __shfl_sync(~0u, qsel, i0) * __shfl_sync(~0u, rsel, j0);
        a1 += __shfl_sync(~0u, qsel, i1) * __shfl_sync(~0u, rsel, j1);
        a2 += __shfl_sync(~0u, qsel, i2) * __shfl_sync(~0u, rsel, j2);
    }

    sslot[wInB][lane]      = a0;
    sslot[wInB][lane + 32] = a1;
    if (lane < 2) sslot[wInB][64 + lane] = a2;

    #pragma unroll
    for (int k = 0; k < 14; k++) {
        float v = (k < 4) ? u1[k] : u2[k - 4];
        #pragma unroll
        for (int off = 16; off; off >>= 1) v += __shfl_xor_sync(~0u, v, off);
        if (lane == 0) su[wInB][k] = v;
    }
    __syncthreads();
    int tid = threadIdx.x;
    if (tid < 66) {
        float s = 0.f;
        #pragma unroll
        for (int w = 0; w < 8; w++) s += sslot[w][tid];
        g_part[blockIdx.x][tid] = s;
    } else if (tid < 80) {
        float s = 0.f;
        #pragma unroll
        for (int w = 0; w < 8; w++) s += su[w][tid - 66];
        g_part[blockIdx.x][tid] = s;
    }
}

// ---------------- kernel B: reconstruct moments, finalize BN, fold weights --
__global__ void __launch_bounds__(1024) kbn(const float* __restrict__ W,
                                            const float* __restrict__ gamma,
                                            const float* __restrict__ beta) {
    __shared__ float tot[80];
    __shared__ float T2s[10][10];
    __shared__ float T1s[10];
    __shared__ float s_scale[COUTn];
    int tid = threadIdx.x, lane = tid & 31, w = tid >> 5;

    for (int k = w; k < 80; k += 32) {
        float s = 0.f;
        for (int j = lane; j < SBLOCKS; j += 32) s += g_part[j][k];
        #pragma unroll
        for (int off = 16; off; off >>= 1) s += __shfl_xor_sync(~0u, s, off);
        if (lane == 0) tot[k] = s;
    }
    __syncthreads();
    if (tid < 100) {
        int i = tid / 10, j = tid % 10;
        int mi = (i < 4) ? i : (i - 4) % 3;
        int mj = (j < 4) ? j : (j - 4) % 3;
        int aa = min(mi, mj), bb = max(mi, mj);
        float v = tot[70 + 4*aa - (aa*(aa+1))/2 + bb];         // U2
        if (i >= 4) v -= tot[(i - 4) * 11 + mj];               // -k_i . S_uj
        if (j >= 4) v -= tot[(j - 4) * 11 + mi];               // -k_j . S_ui
        if (i >= 4 && j >= 4) v += 32.f * tot[(i - 4) * 11 + 4 + (j - 4)];
        T2s[i][j] = v;
    }
    if (tid < 10)
        T1s[tid] = (tid < 4) ? tot[66 + tid]
                             : tot[66 + (tid - 4) % 3] - tot[(tid - 4) * 11 + 10];
    __syncthreads();
    if (tid < COUTn) {
        int c = tid;
        float wc[10];
        #pragma unroll
        for (int i = 0; i < 10; i++) wc[i] = W[i * COUTn + c];
        float mu = 0.f, e2 = 0.f;
        #pragma unroll
        for (int i = 0; i < 10; i++) {
            mu += T1s[i] * wc[i];
            float t = 0.f;
            #pragma unroll
            for (int j = 0; j < 10; j++) t += T2s[i][j] * wc[j];
            e2 += wc[i] * t;
        }
        mu = mu / (float)NSAMP;
        e2 = e2 / (float)NSAMP;
        float var = e2 - mu * mu;
        float sc = gamma[c] * rsqrtf(var + 1e-3f);
        s_scale[c] = sc;
        g_shift[c] = beta[c] - mu * sc;
    }
    __syncthreads();
    if (tid < 10 * COUTn) {
        int i = tid >> 6, c = tid & 63;
        float v;
        if (i < 3) v = W[i*COUTn + c] + W[(i+4)*COUTn + c] + W[(i+7)*COUTn + c];
        else       v = W[i*COUTn + c];
        g_wf[tid] = v * s_scale[c];
    }
}

// ---------------- kernel C: decomposed GEMM + max over M + epilogue ---------
// h[m,c] = x*A + y*B + z*C + w*D + E_pc ; pv = relu(max_m(dot) + E + shift)
__global__ void __launch_bounds__(256) kpv(const float4* __restrict__ pil,
                                           const int4*  __restrict__ coords,
                                           const int*   __restrict__ npts) {
    __shared__ __align__(16) float fs[8][4][32];
    int lane = threadIdx.x & 31;
    int wInB = threadIdx.x >> 5;
    int warp = (blockIdx.x * 256 + threadIdx.x) >> 5;
    int c0 = lane, c1 = lane + 32;

    u64 wv0[4], wv1[4];
    #pragma unroll
    for (int i = 0; i < 4; i++) {
        float t = g_wf[i * COUTn + c0]; wv0[i] = pk2(t, t);
        t       = g_wf[i * COUTn + c1]; wv1[i] = pk2(t, t);
    }
    float ew0[6], ew1[6];
    #pragma unroll
    for (int i = 0; i < 6; i++) {
        ew0[i] = g_wf[(4 + i) * COUTn + c0];
        ew1[i] = g_wf[(4 + i) * COUTn + c1];
    }
    float sh0 = g_shift[c0], sh1 = g_shift[c1];

    for (int p = warp; p < Pn; p += CWARPS) {
        float4 pt = pil[p * Mn + lane];
        float sx = pt.x, sy = pt.y, sz = pt.z;
        #pragma unroll
        for (int off = 16; off; off >>= 1) {
            sx += __shfl_xor_sync(~0u, sx, off);
            sy += __shfl_xor_sync(~0u, sy, off);
            sz += __shfl_xor_sync(~0u, sz, off);
        }
        float inv = __fdividef(1.0f, (float)npts[p]);
        int4 cd = coords[p];
        float qa = sx * inv, qb = sy * inv, qc = sz * inv;
        float qd = fmaf((float)cd.w, 0.16f, 0.08f);
        float qe = fmaf((float)cd.z, 0.16f, -39.6f);
        float qg = fmaf((float)cd.y, 4.0f,  -1.0f);
        float E0 = -(qa*ew0[0] + qb*ew0[1] + qc*ew0[2] + qd*ew0[3] + qe*ew0[4] + qg*ew0[5]);
        float E1 = -(qa*ew1[0] + qb*ew1[1] + qc*ew1[2] + qd*ew1[3] + qe*ew1[4] + qg*ew1[5]);

        fs[wInB][0][lane] = pt.x;
        fs[wInB][1][lane] = pt.y;
        fs[wInB][2][lane] = pt.z;
        fs[wInB][3][lane] = pt.w;
        __syncwarp();

        // packed FFMA2 dot; max kept as scalar FMNMX on the two lanes
        // (mov.b64 unpack is register-pair aliasing, ~free; FMNMX rides alu pipe)
        float m0lo = -3.402823466e38f, m0hi = -3.402823466e38f;
        float m1lo = -3.402823466e38f, m1hi = -3.402823466e38f;
        #pragma unroll
        for (int mm = 0; mm < 16; mm++) {
            u64 xp = *reinterpret_cast<const u64*>(&fs[wInB][0][2 * mm]);
            u64 yp = *reinterpret_cast<const u64*>(&fs[wInB][1][2 * mm]);
            u64 zp = *reinterpret_cast<const u64*>(&fs[wInB][2][2 * mm]);
            u64 wp = *reinterpret_cast<const u64*>(&fs[wInB][3][2 * mm]);
            u64 acc = fmul2(wp, wv0[3]);
            acc = ffma2(zp, wv0[2], acc);
            acc = ffma2(yp, wv0[1], acc);
            acc = ffma2(xp, wv0[0], acc);
            float lo, hi; upk2(acc, lo, hi);
            m0lo = fmaxf(m0lo, lo); m0hi = fmaxf(m0hi, hi);
            acc = fmul2(wp, wv1[3]);
            acc = ffma2(zp, wv1[2], acc);
            acc = ffma2(yp, wv1[1], acc);
            acc = ffma2(xp, wv1[0], acc);
            upk2(acc, lo, hi);
            m1lo = fmaxf(m1lo, lo); m1hi = fmaxf(m1hi, hi);
        }
        g_pv[p * COUTn + c0] = fmaxf(fmaxf(m0lo, m0hi) + E0 + sh0, 0.f);
        g_pv[p * COUTn + c1] = fmaxf(fmaxf(m1lo, m1hi) + E1 + sh1, 0.f);
        __syncwarp();
    }
}

// ---------------- kernel Z: write zero quads (depends only on winner) -------
__global__ void __launch_bounds__(256) kzero(float* __restrict__ out) {
    int q = blockIdx.x * 256 + threadIdx.x;          // quad within one batch plane
    if (q >= NCELL / 4) return;
    int b = blockIdx.y;
    int4 w = reinterpret_cast<const int4*>(g_winner)[b * (NCELL / 4) + q];
    if (max(max(w.x, w.y), max(w.z, w.w)) >= 0) return;   // occupied -> kscatter's quad
    float4 z = make_float4(0.f, 0.f, 0.f, 0.f);
    float* base = out + (size_t)b * COUTn * NCELL + (size_t)q * 4;
    #pragma unroll
    for (int cidx = 0; cidx < COUTn; cidx++)
        *reinterpret_cast<float4*>(base + (size_t)cidx * NCELL) = z;
}

// ---------------- kernel S: gather pv into occupied quads -------------------
__global__ void __launch_bounds__(256) kscatter(float* __restrict__ out) {
    int q = blockIdx.x * 256 + threadIdx.x;
    if (q >= NCELL / 4) return;
    int b = blockIdx.y;
    int4 w = reinterpret_cast<const int4*>(g_winner)[b * (NCELL / 4) + q];
    if (max(max(w.x, w.y), max(w.z, w.w)) < 0) return;    // empty -> kzero's quad
    const float4 z = make_float4(0.f, 0.f, 0.f, 0.f);
    float* base = out + (size_t)b * COUTn * NCELL + (size_t)q * 4;
    #pragma unroll 4
    for (int cc = 0; cc < COUTn; cc += 4) {
        float4 r0 = (w.x >= 0) ? *reinterpret_cast<const float4*>(&g_pv[w.x * COUTn + cc]) : z;
        float4 r1 = (w.y >= 0) ? *reinterpret_cast<const float4*>(&g_pv[w.y * COUTn + cc]) : z;
        float4 r2 = (w.z >= 0) ? *reinterpret_cast<const float4*>(&g_pv[w.z * COUTn + cc]) : z;
        float4 r3 = (w.w >= 0) ? *reinterpret_cast<const float4*>(&g_pv[w.w * COUTn + cc]) : z;
        *reinterpret_cast<float4*>(base + (size_t)(cc + 0) * NCELL) = make_float4(r0.x, r1.x, r2.x, r3.x);
        *reinterpret_cast<float4*>(base + (size_t)(cc + 1) * NCELL) = make_float4(r0.y, r1.y, r2.y, r3.y);
        *reinterpret_cast<float4*>(base + (size_t)(cc + 2) * NCELL) = make_float4(r0.z, r1.z, r2.z, r3.z);
        *reinterpret_cast<float4*>(base + (size_t)(cc + 3) * NCELL) = make_float4(r0.w, r1.w, r2.w, r3.w);
    }
}

// ---------------- launch -----------------------------------------------------
extern "C" void kernel_launch(void* const* d_in, const int* in_sizes, int n_in,
                              void* d_out, int out_size) {
    const float4* pil    = (const float4*)d_in[0];   // (96000, 32, 4) f32
    const int4*   coords = (const int4*)  d_in[1];   // (96000, 4) i32
    const int*    npts   = (const int*)   d_in[2];   // (96000,)   i32
    const float*  W      = (const float*) d_in[3];   // (10, 64)   f32
    const float*  gamma  = (const float*) d_in[4];   // (64,)
    const float*  beta   = (const float*) d_in[5];   // (64,)
    float* out = (float*)d_out;
    (void)in_sizes; (void)n_in; (void)out_size;

    static cudaStream_t s2 = nullptr;
    static cudaEvent_t evA = nullptr, evW = nullptr, evB = nullptr;
    if (!s2) {
        cudaStreamCreateWithFlags(&s2, cudaStreamNonBlocking);
        cudaEventCreateWithFlags(&evA, cudaEventDisableTiming);
        cudaEventCreateWithFlags(&evW, cudaEventDisableTiming);
        cudaEventCreateWithFlags(&evB, cudaEventDisableTiming);
    }

    dim3 qgrid((NCELL / 4 + 255) / 256, NBn);        // (210, 8)

    // side branch: winner init/resolve + zero-fill (81% of output bytes),
    // fully concurrent with the compute chain
    cudaEventRecord(evA, 0);
    cudaStreamWaitEvent(s2, evA, 0);
    kfill_winner<<<TOTCELL / 4 / 256, 256, 0, s2>>>();
    kwin<<<(Pn + 255) / 256, 256, 0, s2>>>(coords);
    cudaEventRecord(evW, s2);                        // winner ready
    kzero<<<qgrid, 256, 0, s2>>>(out);
    cudaEventRecord(evB, s2);

    // compute chain
    kstats<<<SBLOCKS, 256>>>(pil, coords, npts);
    kbn<<<1, 1024>>>(W, gamma, beta);
    kpv<<<CBLOCKS, 256>>>(pil, coords, npts);
    cudaStreamWaitEvent(0, evW, 0);
    kscatter<<<qgrid, 256>>>(out);                   // disjoint quads vs kzero

    cudaStreamWaitEvent(0, evB, 0);                  // join before capture end
}